// round 1
// baseline (speedup 1.0000x reference)
#include <cuda_runtime.h>
#include <stdint.h>

// ---------------- problem constants (B=16, H=W=64, A=9, K=50) ----------------
#define A_LOC 9
#define HW    64
#define LOCS  (HW*HW)          // 4096
#define NANCH (LOCS*A_LOC)     // 36864
#define MAXB  16
#define MAXK  64

// ---------------- device scratch (no allocations allowed) --------------------
__device__ float          g_maxovr[MAXB*NANCH];
__device__ unsigned char  g_arg   [MAXB*NANCH];
__device__ signed char    g_lbl   [MAXB*NANCH];   // -2 outside, -1 dontcare, 0 bg, 1 fg
__device__ unsigned int   g_prio  [MAXB*NANCH];   // 23-bit uniform mantissa bits
__device__ int            g_gtmax [MAXB*MAXK];    // float bits (>=0) via atomicMax
__device__ float          g_uw    [MAXB];

// 9 base anchors (exact integers), order: ratio {0.5,1,2} x scale {8,16,32}
__constant__ float c_base[36] = {
  -84.f, -40.f,  99.f,  55.f,
 -176.f, -88.f, 191.f, 103.f,
 -360.f,-184.f, 375.f, 199.f,
  -56.f, -56.f,  71.f,  71.f,
 -120.f,-120.f, 135.f, 135.f,
 -248.f,-248.f, 263.f, 263.f,
  -36.f, -80.f,  51.f,  95.f,
  -80.f,-168.f,  95.f, 183.f,
 -168.f,-344.f, 183.f, 359.f
};

// ---------------- threefry2x32 (20 rounds), matches jax threefry2x32_p -------
__device__ __forceinline__ void tf_round(unsigned &x0, unsigned &x1, int r){
  x0 += x1; x1 = (x1 << r) | (x1 >> (32 - r)); x1 ^= x0;
}
__device__ __forceinline__ uint2 threefry(unsigned k0, unsigned k1,
                                          unsigned x0, unsigned x1){
  unsigned k2 = k0 ^ k1 ^ 0x1BD11BDAu;
  x0 += k0; x1 += k1;
  tf_round(x0,x1,13); tf_round(x0,x1,15); tf_round(x0,x1,26); tf_round(x0,x1,6);
  x0 += k1; x1 += k2 + 1u;
  tf_round(x0,x1,17); tf_round(x0,x1,29); tf_round(x0,x1,16); tf_round(x0,x1,24);
  x0 += k2; x1 += k0 + 2u;
  tf_round(x0,x1,13); tf_round(x0,x1,15); tf_round(x0,x1,26); tf_round(x0,x1,6);
  x0 += k0; x1 += k1 + 3u;
  tf_round(x0,x1,17); tf_round(x0,x1,29); tf_round(x0,x1,16); tf_round(x0,x1,24);
  x0 += k1; x1 += k2 + 4u;
  tf_round(x0,x1,13); tf_round(x0,x1,15); tf_round(x0,x1,26); tf_round(x0,x1,6);
  x0 += k2; x1 += k0 + 5u;
  return make_uint2(x0, x1);
}
// partitionable random_bits(32): bits = b1 ^ b2 of block (hi=0, lo=index)
__device__ __forceinline__ unsigned uniform_m23(uint2 key, unsigned idx){
  uint2 r = threefry(key.x, key.y, 0u, idx);
  return (r.x ^ r.y) >> 9;   // 23-bit mantissa bits; monotone in the uniform value
}

// ---------------- kernel 0: init ---------------------------------------------
__global__ void k_init(){
  for (int i = threadIdx.x; i < MAXB*MAXK; i += blockDim.x) g_gtmax[i] = 0;
}

// ---------------- kernel 1: IoU, max/arg, gt_max -----------------------------
__global__ void k_iou(const float* __restrict__ gt, const float* __restrict__ iminfo, int K){
  int b = blockIdx.y;
  __shared__ float s_g[MAXK][4];
  __shared__ float s_ga[MAXK];
  __shared__ int   s_gm[MAXK];
  int t = threadIdx.x;
  if (t < K){
    float g0 = gt[(b*K+t)*5+0], g1 = gt[(b*K+t)*5+1];
    float g2 = gt[(b*K+t)*5+2], g3 = gt[(b*K+t)*5+3];
    s_g[t][0]=g0; s_g[t][1]=g1; s_g[t][2]=g2; s_g[t][3]=g3;
    s_ga[t] = __fmul_rn(__fadd_rn(__fsub_rn(g2,g0),1.f),
                        __fadd_rn(__fsub_rn(g3,g1),1.f));
    s_gm[t] = 0;
  }
  __syncthreads();

  int n   = blockIdx.x*blockDim.x + t;
  int loc = n / A_LOC, a = n % A_LOC;
  int x = loc & (HW-1), y = loc >> 6;
  float ax1 = c_base[a*4+0] + 16.f*(float)x;
  float ay1 = c_base[a*4+1] + 16.f*(float)y;
  float ax2 = c_base[a*4+2] + 16.f*(float)x;
  float ay2 = c_base[a*4+3] + 16.f*(float)y;
  float imh = iminfo[0], imw = iminfo[1];
  bool inside = (ax1 >= 0.f) && (ay1 >= 0.f) && (ax2 < imw) && (ay2 < imh);
  float aw = __fadd_rn(__fsub_rn(ax2,ax1),1.f);
  float ah = __fadd_rn(__fsub_rn(ay2,ay1),1.f);
  float aarea = __fmul_rn(aw, ah);

  float mo = 0.f; int ma = 0;
  for (int k = 0; k < K; k++){
    float ix = fmaxf(0.f, __fadd_rn(__fsub_rn(fminf(ax2,s_g[k][2]), fmaxf(ax1,s_g[k][0])),1.f));
    float iy = fmaxf(0.f, __fadd_rn(__fsub_rn(fminf(ay2,s_g[k][3]), fmaxf(ay1,s_g[k][1])),1.f));
    float inter = __fmul_rn(ix, iy);
    float uni   = __fsub_rn(__fadd_rn(aarea, s_ga[k]), inter);
    float ovr   = __fdiv_rn(inter, uni);
    if (ovr > mo){ mo = ovr; ma = k; }
    unsigned bits = inside ? (unsigned)__float_as_int(ovr) : 0u;
    unsigned wmax = __reduce_max_sync(0xffffffffu, bits);
    if ((t & 31) == 0 && wmax) atomicMax(&s_gm[k], (int)wmax);
  }
  g_maxovr[b*NANCH+n] = inside ? mo : -1.f;
  g_arg   [b*NANCH+n] = (unsigned char)ma;
  __syncthreads();
  if (t < K && s_gm[t]) atomicMax(&g_gtmax[b*MAXK+t], s_gm[t]);
}

// ---------------- kernel 2: labels (recompute IoU, is_best via equality) -----
__global__ void k_label(const float* __restrict__ gt, int K){
  int b = blockIdx.y;
  __shared__ float s_g[MAXK][4];
  __shared__ float s_ga[MAXK];
  __shared__ float s_gmf[MAXK];
  int t = threadIdx.x;
  if (t < K){
    float g0 = gt[(b*K+t)*5+0], g1 = gt[(b*K+t)*5+1];
    float g2 = gt[(b*K+t)*5+2], g3 = gt[(b*K+t)*5+3];
    s_g[t][0]=g0; s_g[t][1]=g1; s_g[t][2]=g2; s_g[t][3]=g3;
    s_ga[t] = __fmul_rn(__fadd_rn(__fsub_rn(g2,g0),1.f),
                        __fadd_rn(__fsub_rn(g3,g1),1.f));
    s_gmf[t] = __int_as_float(g_gtmax[b*MAXK+t]);  // 0 => no inside anchor hits this gt
  }
  __syncthreads();

  int n = blockIdx.x*blockDim.x + t;
  float mo = g_maxovr[b*NANCH+n];
  signed char L;
  if (mo < 0.f){
    L = -2;                                       // outside
  } else {
    L = -1;
    if (mo < 0.3f) L = 0;
    bool best = false;
    if (mo > 0.f){
      int loc = n / A_LOC, a = n % A_LOC;
      int x = loc & (HW-1), y = loc >> 6;
      float ax1 = c_base[a*4+0] + 16.f*(float)x;
      float ay1 = c_base[a*4+1] + 16.f*(float)y;
      float ax2 = c_base[a*4+2] + 16.f*(float)x;
      float ay2 = c_base[a*4+3] + 16.f*(float)y;
      float aw = __fadd_rn(__fsub_rn(ax2,ax1),1.f);
      float ah = __fadd_rn(__fsub_rn(ay2,ay1),1.f);
      float aarea = __fmul_rn(aw, ah);
      for (int k = 0; k < K; k++){
        float gm = s_gmf[k];
        if (gm <= 0.f) continue;                  // gt_max==0 can never match
        float ix = fmaxf(0.f, __fadd_rn(__fsub_rn(fminf(ax2,s_g[k][2]), fmaxf(ax1,s_g[k][0])),1.f));
        float iy = fmaxf(0.f, __fadd_rn(__fsub_rn(fminf(ay2,s_g[k][3]), fmaxf(ay1,s_g[k][1])),1.f));
        float inter = __fmul_rn(ix, iy);
        float uni   = __fsub_rn(__fadd_rn(aarea, s_ga[k]), inter);
        float ovr   = __fdiv_rn(inter, uni);
        if (ovr == gm) best = true;
      }
    }
    if (best) L = 1;
    if (mo >= 0.7f) L = 1;
  }
  g_lbl[b*NANCH+n] = L;
}

// ---------------- kernel 3: per-batch stochastic subsampling -----------------
// Reference: keep top-`limit` masked anchors by (descending uniform, ascending idx).
// Radix select on 23-bit keys: 4096-bin hist (top 12 bits) -> 2048-bin (low 11) ->
// exact boundary value, ties resolved by smallest index (stable argsort semantics).
__device__ int do_select(int b, signed char want, uint2 key, int limit,
                         int* hist, int* hist2, int* s_list, int* s_s){
  int tid = threadIdx.x, nt = blockDim.x;
  if (tid == 0) s_s[0] = 0;
  __syncthreads();
  for (int n = tid; n < NANCH; n += nt){
    if (g_lbl[b*NANCH+n] == want){
      atomicAdd(&s_s[0], 1);
      g_prio[b*NANCH+n] = uniform_m23(key, (unsigned)n);
    }
  }
  __syncthreads();
  int cnt = s_s[0];
  if (cnt <= limit) return cnt;                   // nothing disabled

  for (int i = tid; i < 4096; i += nt) hist[i] = 0;
  __syncthreads();
  for (int n = tid; n < NANCH; n += nt)
    if (g_lbl[b*NANCH+n] == want) atomicAdd(&hist[g_prio[b*NANCH+n] >> 11], 1);
  __syncthreads();
  if (tid == 0){
    int acc = 0;
    for (int v = 4095; v >= 0; v--){
      acc += hist[v];
      if (acc >= limit){ s_s[2] = v; s_s[3] = limit - (acc - hist[v]); break; }
    }
  }
  __syncthreads();
  int bin = s_s[2], rem = s_s[3];
  for (int i = tid; i < 2048; i += nt) hist2[i] = 0;
  __syncthreads();
  for (int n = tid; n < NANCH; n += nt){
    if (g_lbl[b*NANCH+n] == want){
      unsigned m = g_prio[b*NANCH+n];
      if ((int)(m >> 11) == bin) atomicAdd(&hist2[m & 2047], 1);
    }
  }
  __syncthreads();
  if (tid == 0){
    int acc = 0;
    for (int u = 2047; u >= 0; u--){
      acc += hist2[u];
      if (acc >= rem){ s_s[4] = (bin << 11) | u; s_s[5] = rem - (acc - hist2[u]); break; }
    }
    s_s[1] = 0;
  }
  __syncthreads();
  unsigned tval = (unsigned)s_s[4]; int r = s_s[5];
  for (int n = tid; n < NANCH; n += nt){
    if (g_lbl[b*NANCH+n] == want && g_prio[b*NANCH+n] == tval){
      int p = atomicAdd(&s_s[1], 1);
      if (p < 512) s_list[p] = n;
    }
  }
  __syncthreads();
  if (tid == 0){
    int ec = s_s[1]; if (ec > 512) ec = 512;
    for (int i = 1; i < ec; i++){                 // insertion sort asc (ec tiny)
      int v = s_list[i]; int j = i - 1;
      while (j >= 0 && s_list[j] > v){ s_list[j+1] = s_list[j]; j--; }
      s_list[j+1] = v;
    }
    for (int j = r; j < ec; j++) g_lbl[b*NANCH + s_list[j]] = -1;
  }
  __syncthreads();
  for (int n = tid; n < NANCH; n += nt)
    if (g_lbl[b*NANCH+n] == want && g_prio[b*NANCH+n] < tval) g_lbl[b*NANCH+n] = -1;
  __syncthreads();
  return limit;
}

__global__ void k_sub(){
  int b = blockIdx.x;
  __shared__ int hist[4096];
  __shared__ int hist2[2048];
  __shared__ int s_list[512];
  __shared__ int s_s[8];
  __shared__ uint2 s_kf, s_kb;
  if (threadIdx.x == 0){
    // jax.random.key(42) -> (0,42); foldlike split: key_b = block(root, 0, b)
    uint2 kb_root = threefry(0u, 42u, 0u, (unsigned)b);
    s_kf = threefry(kb_root.x, kb_root.y, 0u, 0u);
    s_kb = threefry(kb_root.x, kb_root.y, 0u, 1u);
  }
  __syncthreads();
  int kept_fg = do_select(b, 1, s_kf, 128, hist, hist2, s_list, s_s);
  int limit_bg = 256 - kept_fg;
  int kept_bg = do_select(b, 0, s_kb, limit_bg, hist, hist2, s_list, s_s);
  if (threadIdx.x == 0)
    g_uw[b] = __fdiv_rn(1.f, (float)(kept_fg + kept_bg));
}

// ---------------- kernel 4: targets + transposed output writer ---------------
__global__ void k_out(const float* __restrict__ gt, float* __restrict__ out, int B, int K){
  int b = blockIdx.z, a = blockIdx.y;
  int loc = blockIdx.x*blockDim.x + threadIdx.x;
  __shared__ float s_g[MAXK][4];
  if (threadIdx.x < K){
    int t = threadIdx.x;
    s_g[t][0] = gt[(b*K+t)*5+0]; s_g[t][1] = gt[(b*K+t)*5+1];
    s_g[t][2] = gt[(b*K+t)*5+2]; s_g[t][3] = gt[(b*K+t)*5+3];
  }
  __syncthreads();

  int n = loc*A_LOC + a;
  signed char L = g_lbl[b*NANCH+n];
  float lab = (L == -2) ? 0.f : (float)L;

  size_t labOff = (size_t)b*NANCH + (size_t)a*LOCS + loc;
  out[labOff] = lab;

  float t0=0.f, t1=0.f, t2=0.f, t3=0.f, iw=0.f, ow=0.f;
  if (L != -2){
    int x = loc & (HW-1), y = loc >> 6;
    float ax1 = c_base[a*4+0] + 16.f*(float)x;
    float ay1 = c_base[a*4+1] + 16.f*(float)y;
    float ax2 = c_base[a*4+2] + 16.f*(float)x;
    float ay2 = c_base[a*4+3] + 16.f*(float)y;
    float aw = ax2-ax1+1.f, ah = ay2-ay1+1.f;
    float acx = ax1 + 0.5f*(aw-1.f), acy = ay1 + 0.5f*(ah-1.f);
    int k = g_arg[b*NANCH+n];
    float g0 = s_g[k][0], g1 = s_g[k][1], g2 = s_g[k][2], g3 = s_g[k][3];
    float gw = g2-g0+1.f, gh = g3-g1+1.f;
    float gcx = g0 + 0.5f*(gw-1.f), gcy = g1 + 0.5f*(gh-1.f);
    t0 = (gcx-acx)/aw; t1 = (gcy-acy)/ah;
    t2 = logf(gw/aw);  t3 = logf(gh/ah);
    iw = (L == 1) ? 1.f : 0.f;
    ow = (L == 0 || L == 1) ? g_uw[b] : 0.f;
  }
  size_t base_t  = (size_t)B*NANCH;
  size_t planes  = (size_t)B*36*LOCS;
  size_t p       = ((size_t)b*36 + (size_t)a*4)*LOCS + loc;
  float tv[4] = {t0,t1,t2,t3};
#pragma unroll
  for (int j = 0; j < 4; j++){
    out[base_t              + p + (size_t)j*LOCS] = tv[j];
    out[base_t +   planes   + p + (size_t)j*LOCS] = iw;
    out[base_t + 2*planes   + p + (size_t)j*LOCS] = ow;
  }
}

// ---------------- launch -----------------------------------------------------
extern "C" void kernel_launch(void* const* d_in, const int* in_sizes, int n_in,
                              void* d_out, int out_size){
  const float* gt     = (const float*)d_in[1];
  const float* iminfo = (const float*)d_in[2];
  float* out = (float*)d_out;

  int B = in_sizes[0] / (2*A_LOC*LOCS);     // rpn_cls_score: B x 18 x 64 x 64
  int K = in_sizes[1] / (5*B);              // gt_boxes:      B x K x 5
  if (B > MAXB) B = MAXB;
  if (K > MAXK) K = MAXK;

  k_init<<<1, 256>>>();
  dim3 g1(NANCH/256, B);
  k_iou  <<<g1, 256>>>(gt, iminfo, K);
  k_label<<<g1, 256>>>(gt, K);
  k_sub  <<<B, 1024>>>();
  k_out  <<<dim3(LOCS/256, A_LOC, B), 256>>>(gt, out, B, K);
}

// round 2
// speedup vs baseline: 2.4755x; 2.4755x over previous
#include <cuda_runtime.h>
#include <stdint.h>

// ---------------- problem constants (B=16, H=W=64, A=9, K=50) ----------------
#define A_LOC 9
#define HW    64
#define LOCS  (HW*HW)          // 4096
#define NANCH (LOCS*A_LOC)     // 36864
#define MAXB  16
#define MAXK  64

// ---------------- device scratch (no allocations allowed) --------------------
__device__ float              g_maxovr[MAXB*NANCH];
__device__ unsigned char      g_arg   [MAXB*NANCH];
__device__ signed char        g_lbl   [MAXB*NANCH];   // -2 outside, -1 dontcare, 0 bg, 1 fg
__device__ int                g_gtmax [MAXB*MAXK];    // float bits (>=0) via atomicMax
__device__ float              g_uw    [MAXB];
__device__ uint4              g_keys  [MAXB];         // (kf.x,kf.y,kb.x,kb.y) per batch
__device__ int                g_cnt   [MAXB*2];       // fg,bg candidate counts
__device__ unsigned long long g_fg    [MAXB*NANCH];   // (prio<<32)|n
__device__ unsigned long long g_bg    [MAXB*NANCH];

// 9 base anchors (exact integers), order: ratio {0.5,1,2} x scale {8,16,32}
__constant__ float c_base[36] = {
  -84.f, -40.f,  99.f,  55.f,
 -176.f, -88.f, 191.f, 103.f,
 -360.f,-184.f, 375.f, 199.f,
  -56.f, -56.f,  71.f,  71.f,
 -120.f,-120.f, 135.f, 135.f,
 -248.f,-248.f, 263.f, 263.f,
  -36.f, -80.f,  51.f,  95.f,
  -80.f,-168.f,  95.f, 183.f,
 -168.f,-344.f, 183.f, 359.f
};

// ---------------- threefry2x32 (20 rounds), matches jax threefry2x32_p -------
__device__ __forceinline__ void tf_round(unsigned &x0, unsigned &x1, int r){
  x0 += x1; x1 = (x1 << r) | (x1 >> (32 - r)); x1 ^= x0;
}
__device__ __forceinline__ uint2 threefry(unsigned k0, unsigned k1,
                                          unsigned x0, unsigned x1){
  unsigned k2 = k0 ^ k1 ^ 0x1BD11BDAu;
  x0 += k0; x1 += k1;
  tf_round(x0,x1,13); tf_round(x0,x1,15); tf_round(x0,x1,26); tf_round(x0,x1,6);
  x0 += k1; x1 += k2 + 1u;
  tf_round(x0,x1,17); tf_round(x0,x1,29); tf_round(x0,x1,16); tf_round(x0,x1,24);
  x0 += k2; x1 += k0 + 2u;
  tf_round(x0,x1,13); tf_round(x0,x1,15); tf_round(x0,x1,26); tf_round(x0,x1,6);
  x0 += k0; x1 += k1 + 3u;
  tf_round(x0,x1,17); tf_round(x0,x1,29); tf_round(x0,x1,16); tf_round(x0,x1,24);
  x0 += k1; x1 += k2 + 4u;
  tf_round(x0,x1,13); tf_round(x0,x1,15); tf_round(x0,x1,26); tf_round(x0,x1,6);
  x0 += k2; x1 += k0 + 5u;
  return make_uint2(x0, x1);
}
// partitionable random_bits(32): bits = b1 ^ b2 of block (hi=0, lo=index)
__device__ __forceinline__ unsigned uniform_m23(unsigned k0, unsigned k1, unsigned idx){
  uint2 r = threefry(k0, k1, 0u, idx);
  return (r.x ^ r.y) >> 9;   // 23-bit mantissa bits; monotone in the uniform value
}

// ---------------- kernel 0: init + per-batch PRNG keys -----------------------
__global__ void k_init(){
  int t = threadIdx.x;
  for (int i = t; i < MAXB*MAXK; i += blockDim.x) g_gtmax[i] = 0;
  if (t < MAXB*2) g_cnt[t] = 0;
  if (t < MAXB){
    // jax.random.key(42) -> (0,42); foldlike split: key_b = block(root, 0, b)
    uint2 root = threefry(0u, 42u, 0u, (unsigned)t);
    uint2 kf = threefry(root.x, root.y, 0u, 0u);
    uint2 kb = threefry(root.x, root.y, 0u, 1u);
    g_keys[t] = make_uint4(kf.x, kf.y, kb.x, kb.y);
  }
}

// ---------------- kernel 1: IoU, max/arg, gt_max -----------------------------
__global__ void k_iou(const float* __restrict__ gt, const float* __restrict__ iminfo, int K){
  int b = blockIdx.y;
  __shared__ float s_g[MAXK][4];
  __shared__ float s_ga[MAXK];
  __shared__ int   s_gm[MAXK];
  int t = threadIdx.x;
  if (t < K){
    float g0 = gt[(b*K+t)*5+0], g1 = gt[(b*K+t)*5+1];
    float g2 = gt[(b*K+t)*5+2], g3 = gt[(b*K+t)*5+3];
    s_g[t][0]=g0; s_g[t][1]=g1; s_g[t][2]=g2; s_g[t][3]=g3;
    s_ga[t] = __fmul_rn(__fadd_rn(__fsub_rn(g2,g0),1.f),
                        __fadd_rn(__fsub_rn(g3,g1),1.f));
    s_gm[t] = 0;
  }
  __syncthreads();

  int n   = blockIdx.x*blockDim.x + t;
  int loc = n / A_LOC, a = n % A_LOC;
  int x = loc & (HW-1), y = loc >> 6;
  float ax1 = c_base[a*4+0] + 16.f*(float)x;
  float ay1 = c_base[a*4+1] + 16.f*(float)y;
  float ax2 = c_base[a*4+2] + 16.f*(float)x;
  float ay2 = c_base[a*4+3] + 16.f*(float)y;
  float imh = iminfo[0], imw = iminfo[1];
  bool inside = (ax1 >= 0.f) && (ay1 >= 0.f) && (ax2 < imw) && (ay2 < imh);
  float aw = __fadd_rn(__fsub_rn(ax2,ax1),1.f);
  float ah = __fadd_rn(__fsub_rn(ay2,ay1),1.f);
  float aarea = __fmul_rn(aw, ah);

  float mo = 0.f; int ma = 0;
  for (int k = 0; k < K; k++){
    float ix = fmaxf(0.f, __fadd_rn(__fsub_rn(fminf(ax2,s_g[k][2]), fmaxf(ax1,s_g[k][0])),1.f));
    float iy = fmaxf(0.f, __fadd_rn(__fsub_rn(fminf(ay2,s_g[k][3]), fmaxf(ay1,s_g[k][1])),1.f));
    float inter = __fmul_rn(ix, iy);
    float uni   = __fsub_rn(__fadd_rn(aarea, s_ga[k]), inter);
    float ovr   = __fdiv_rn(inter, uni);
    if (ovr > mo){ mo = ovr; ma = k; }
    unsigned bits = inside ? (unsigned)__float_as_int(ovr) : 0u;
    unsigned wmax = __reduce_max_sync(0xffffffffu, bits);
    if ((t & 31) == 0 && wmax) atomicMax(&s_gm[k], (int)wmax);
  }
  g_maxovr[b*NANCH+n] = inside ? mo : -1.f;
  g_arg   [b*NANCH+n] = (unsigned char)ma;
  __syncthreads();
  if (t < K && s_gm[t]) atomicMax(&g_gtmax[b*MAXK+t], s_gm[t]);
}

// ---------------- kernel 2: labels + fused candidate compaction --------------
__global__ void k_label(const float* __restrict__ gt, int K){
  int b = blockIdx.y;
  __shared__ float s_g[MAXK][4];
  __shared__ float s_ga[MAXK];
  __shared__ float s_gmf[MAXK];
  __shared__ float s_gmin;
  int t = threadIdx.x;
  if (t < K){
    float g0 = gt[(b*K+t)*5+0], g1 = gt[(b*K+t)*5+1];
    float g2 = gt[(b*K+t)*5+2], g3 = gt[(b*K+t)*5+3];
    s_g[t][0]=g0; s_g[t][1]=g1; s_g[t][2]=g2; s_g[t][3]=g3;
    s_ga[t] = __fmul_rn(__fadd_rn(__fsub_rn(g2,g0),1.f),
                        __fadd_rn(__fsub_rn(g3,g1),1.f));
    s_gmf[t] = __int_as_float(g_gtmax[b*MAXK+t]);  // 0 => no inside anchor hits this gt
  }
  __syncthreads();
  if (t == 0){
    float mn = 1e30f;
    for (int k = 0; k < K; k++){ float g = s_gmf[k]; if (g > 0.f && g < mn) mn = g; }
    s_gmin = mn;
  }
  __syncthreads();

  int n = blockIdx.x*blockDim.x + t;
  float mo = g_maxovr[b*NANCH+n];
  // warp max of mo (all mo's here are either -1 or >=0; clamp to 0 for bits order)
  unsigned wmb = __reduce_max_sync(0xffffffffu, (unsigned)__float_as_int(fmaxf(mo, 0.f)));
  float wmo = __uint_as_float(wmb);

  signed char L;
  if (mo < 0.f){
    L = -2;                                       // outside
  } else {
    L = (mo < 0.3f) ? 0 : -1;
    bool best = false;
    if (wmo > 0.f && wmo >= s_gmin){
      int loc = n / A_LOC, a = n % A_LOC;
      int x = loc & (HW-1), y = loc >> 6;
      float ax1 = c_base[a*4+0] + 16.f*(float)x;
      float ay1 = c_base[a*4+1] + 16.f*(float)y;
      float ax2 = c_base[a*4+2] + 16.f*(float)x;
      float ay2 = c_base[a*4+3] + 16.f*(float)y;
      float aw = __fadd_rn(__fsub_rn(ax2,ax1),1.f);
      float ah = __fadd_rn(__fsub_rn(ay2,ay1),1.f);
      float aarea = __fmul_rn(aw, ah);
      for (int k = 0; k < K; k++){
        float gm = s_gmf[k];
        if (gm <= 0.f || gm > wmo) continue;      // warp-uniform skip
        float ix = fmaxf(0.f, __fadd_rn(__fsub_rn(fminf(ax2,s_g[k][2]), fmaxf(ax1,s_g[k][0])),1.f));
        float iy = fmaxf(0.f, __fadd_rn(__fsub_rn(fminf(ay2,s_g[k][3]), fmaxf(ay1,s_g[k][1])),1.f));
        float inter = __fmul_rn(ix, iy);
        float uni   = __fsub_rn(__fadd_rn(aarea, s_ga[k]), inter);
        float ovr   = __fdiv_rn(inter, uni);
        if (ovr == gm) best = true;
      }
    }
    if (best) L = 1;
    if (mo >= 0.7f) L = 1;
  }
  g_lbl[b*NANCH+n] = L;

  // ---- fused candidate compaction (warp-aggregated global append) ----
  bool isfg = (L == 1), isbg = (L == 0);
  unsigned mfg = __ballot_sync(0xffffffffu, isfg);
  unsigned mbg = __ballot_sync(0xffffffffu, isbg);
  int lane = t & 31;
  if (isfg){
    uint4 kk = g_keys[b];
    unsigned prio = uniform_m23(kk.x, kk.y, (unsigned)n);
    int ldr = __ffs(mfg) - 1;
    int pos;
    if (lane == ldr) pos = atomicAdd(&g_cnt[b*2+0], __popc(mfg));
    pos = __shfl_sync(mfg, pos, ldr);
    pos += __popc(mfg & ((1u << lane) - 1u));
    g_fg[b*NANCH + pos] = ((unsigned long long)prio << 32) | (unsigned)n;
  }
  if (isbg){
    uint4 kk = g_keys[b];
    unsigned prio = uniform_m23(kk.z, kk.w, (unsigned)n);
    int ldr = __ffs(mbg) - 1;
    int pos;
    if (lane == ldr) pos = atomicAdd(&g_cnt[b*2+1], __popc(mbg));
    pos = __shfl_sync(mbg, pos, ldr);
    pos += __popc(mbg & ((1u << lane) - 1u));
    g_bg[b*NANCH + pos] = ((unsigned long long)prio << 32) | (unsigned)n;
  }
}

// ---------------- kernel 3: per-batch subsampling on compacted lists ---------
// Keep top-`limit` entries by (prio desc, index asc); disable the rest.
// Two-level radix select (4096 bins on prio[22:11], 2048 bins on prio[10:0]),
// parallel suffix scans, exact tie handling by smallest index (stable argsort).
__device__ int do_select_list(const unsigned long long* __restrict__ list,
                              int b, int cnt, int limit,
                              int* hist, int* s_sc, int* s_list, int* s_s){
  const int tid = threadIdx.x;
  if (cnt <= limit) return cnt;

  // --- level 1 histogram
  for (int i = tid; i < 4096; i += 1024) hist[i] = 0;
  __syncthreads();
  for (int i = tid; i < cnt; i += 1024){
    unsigned p = (unsigned)(list[i] >> 32);
    atomicAdd(&hist[p >> 11], 1);
  }
  __syncthreads();
  // suffix scan over 1024 groups of 4 bins
  int pp = hist[4*tid] + hist[4*tid+1] + hist[4*tid+2] + hist[4*tid+3];
  s_sc[tid] = pp;
  __syncthreads();
  for (int off = 1; off < 1024; off <<= 1){
    int v = s_sc[tid];
    int w = (tid + off < 1024) ? s_sc[tid + off] : 0;
    __syncthreads();
    s_sc[tid] = v + w;
    __syncthreads();
  }
  {
    int St  = s_sc[tid];
    int Stn = (tid < 1023) ? s_sc[tid+1] : 0;
    if (St >= limit && (tid == 1023 || Stn < limit)){ s_s[0] = tid; s_s[1] = Stn; }
  }
  __syncthreads();
  if (tid == 0){
    int g = s_s[0], acc = s_s[1];
    for (int v = 4*g+3; v >= 4*g; v--){
      acc += hist[v];
      if (acc >= limit){ s_s[2] = v; s_s[3] = limit - (acc - hist[v]); break; }
    }
  }
  __syncthreads();
  int bin = s_s[2], rem = s_s[3];

  // --- level 2 histogram (within boundary bin)
  for (int i = tid; i < 2048; i += 1024) hist[i] = 0;
  __syncthreads();
  for (int i = tid; i < cnt; i += 1024){
    unsigned p = (unsigned)(list[i] >> 32);
    if ((int)(p >> 11) == bin) atomicAdd(&hist[p & 2047], 1);
  }
  __syncthreads();
  int p2 = hist[2*tid] + hist[2*tid+1];
  s_sc[tid] = p2;
  __syncthreads();
  for (int off = 1; off < 1024; off <<= 1){
    int v = s_sc[tid];
    int w = (tid + off < 1024) ? s_sc[tid + off] : 0;
    __syncthreads();
    s_sc[tid] = v + w;
    __syncthreads();
  }
  {
    int St  = s_sc[tid];
    int Stn = (tid < 1023) ? s_sc[tid+1] : 0;
    if (St >= rem && (tid == 1023 || Stn < rem)){ s_s[0] = tid; s_s[1] = Stn; }
  }
  __syncthreads();
  if (tid == 0){
    int g = s_s[0], acc = s_s[1];
    for (int u = 2*g+1; u >= 2*g; u--){
      acc += hist[u];
      if (acc >= rem){ s_s[4] = (bin << 11) | u; s_s[5] = rem - (acc - hist[u]); break; }
    }
    s_s[6] = 0;
  }
  __syncthreads();
  unsigned tval = (unsigned)s_s[4]; int r = s_s[5];

  // --- mark below-threshold disabled, collect exact ties
  for (int i = tid; i < cnt; i += 1024){
    unsigned long long e = list[i];
    unsigned p = (unsigned)(e >> 32);
    int n = (int)(unsigned)e;
    if (p < tval) g_lbl[b*NANCH + n] = -1;
    else if (p == tval){
      int pos = atomicAdd(&s_s[6], 1);
      if (pos < 512) s_list[pos] = n;
    }
  }
  __syncthreads();
  if (tid == 0){
    int ec = s_s[6]; if (ec > 512) ec = 512;
    for (int i = 1; i < ec; i++){                 // insertion sort asc (ec tiny)
      int v = s_list[i]; int j = i - 1;
      while (j >= 0 && s_list[j] > v){ s_list[j+1] = s_list[j]; j--; }
      s_list[j+1] = v;
    }
    for (int j = r; j < ec; j++) g_lbl[b*NANCH + s_list[j]] = -1;
  }
  __syncthreads();
  return limit;
}

__global__ void k_sub(){
  int b = blockIdx.x;
  __shared__ int hist[4096];
  __shared__ int s_sc[1024];
  __shared__ int s_list[512];
  __shared__ int s_s[8];
  int cf = g_cnt[b*2+0];
  int cb = g_cnt[b*2+1];
  int kept_fg = do_select_list(&g_fg[b*NANCH], b, cf, 128, hist, s_sc, s_list, s_s);
  int kept_bg = do_select_list(&g_bg[b*NANCH], b, cb, 256 - kept_fg, hist, s_sc, s_list, s_s);
  if (threadIdx.x == 0)
    g_uw[b] = __fdiv_rn(1.f, (float)(kept_fg + kept_bg));
}

// ---------------- kernel 4: targets + transposed output writer ---------------
__global__ void k_out(const float* __restrict__ gt, float* __restrict__ out, int B, int K){
  int b = blockIdx.z, a = blockIdx.y;
  int loc = blockIdx.x*blockDim.x + threadIdx.x;
  __shared__ float s_g[MAXK][4];
  if (threadIdx.x < K){
    int t = threadIdx.x;
    s_g[t][0] = gt[(b*K+t)*5+0]; s_g[t][1] = gt[(b*K+t)*5+1];
    s_g[t][2] = gt[(b*K+t)*5+2]; s_g[t][3] = gt[(b*K+t)*5+3];
  }
  __syncthreads();

  int n = loc*A_LOC + a;
  signed char L = g_lbl[b*NANCH+n];
  float lab = (L == -2) ? 0.f : (float)L;

  size_t labOff = (size_t)b*NANCH + (size_t)a*LOCS + loc;
  out[labOff] = lab;

  float t0=0.f, t1=0.f, t2=0.f, t3=0.f, iw=0.f, ow=0.f;
  if (L != -2){
    int x = loc & (HW-1), y = loc >> 6;
    float ax1 = c_base[a*4+0] + 16.f*(float)x;
    float ay1 = c_base[a*4+1] + 16.f*(float)y;
    float ax2 = c_base[a*4+2] + 16.f*(float)x;
    float ay2 = c_base[a*4+3] + 16.f*(float)y;
    float aw = ax2-ax1+1.f, ah = ay2-ay1+1.f;
    float acx = ax1 + 0.5f*(aw-1.f), acy = ay1 + 0.5f*(ah-1.f);
    int k = g_arg[b*NANCH+n];
    float g0 = s_g[k][0], g1 = s_g[k][1], g2 = s_g[k][2], g3 = s_g[k][3];
    float gw = g2-g0+1.f, gh = g3-g1+1.f;
    float gcx = g0 + 0.5f*(gw-1.f), gcy = g1 + 0.5f*(gh-1.f);
    t0 = (gcx-acx)/aw; t1 = (gcy-acy)/ah;
    t2 = logf(gw/aw);  t3 = logf(gh/ah);
    iw = (L == 1) ? 1.f : 0.f;
    ow = (L == 0 || L == 1) ? g_uw[b] : 0.f;
  }
  size_t base_t  = (size_t)B*NANCH;
  size_t planes  = (size_t)B*36*LOCS;
  size_t p       = ((size_t)b*36 + (size_t)a*4)*LOCS + loc;
  float tv[4] = {t0,t1,t2,t3};
#pragma unroll
  for (int j = 0; j < 4; j++){
    out[base_t              + p + (size_t)j*LOCS] = tv[j];
    out[base_t +   planes   + p + (size_t)j*LOCS] = iw;
    out[base_t + 2*planes   + p + (size_t)j*LOCS] = ow;
  }
}

// ---------------- launch -----------------------------------------------------
extern "C" void kernel_launch(void* const* d_in, const int* in_sizes, int n_in,
                              void* d_out, int out_size){
  const float* gt     = (const float*)d_in[1];
  const float* iminfo = (const float*)d_in[2];
  float* out = (float*)d_out;

  int B = in_sizes[0] / (2*A_LOC*LOCS);     // rpn_cls_score: B x 18 x 64 x 64
  int K = in_sizes[1] / (5*B);              // gt_boxes:      B x K x 5
  if (B > MAXB) B = MAXB;
  if (K > MAXK) K = MAXK;

  k_init<<<1, 256>>>();
  dim3 g1(NANCH/256, B);
  k_iou  <<<g1, 256>>>(gt, iminfo, K);
  k_label<<<g1, 256>>>(gt, K);
  k_sub  <<<B, 1024>>>();
  k_out  <<<dim3(LOCS/256, A_LOC, B), 256>>>(gt, out, B, K);
}

// round 3
// speedup vs baseline: 4.6946x; 1.8964x over previous
#include <cuda_runtime.h>
#include <stdint.h>

// ---------------- problem constants (B=16, H=W=64, A=9, K=50) ----------------
#define A_LOC 9
#define HW    64
#define LOCS  (HW*HW)          // 4096
#define NANCH (LOCS*A_LOC)     // 36864
#define MAXB  16
#define MAXK  64
#define SLOTS 6

// shape-major storage index for anchor (a, loc):  a*LOCS + loc
// original (reference) anchor index:              loc*A_LOC + a

// ---------------- device scratch (no allocations allowed) --------------------
__device__ float              g_maxovr[MAXB*NANCH];     // shape-major; -1 = outside
__device__ unsigned char      g_arg   [MAXB*NANCH];     // shape-major
__device__ signed char        g_lbl   [MAXB*NANCH];     // shape-major; -2 out,-1 dc,0 bg,1 fg
__device__ unsigned char      g_ccnt  [MAXB*NANCH];     // candidate count (sat 255)
__device__ unsigned long long g_cand  [(size_t)MAXB*NANCH*SLOTS]; // (ovr_bits<<32)|k
__device__ int                g_gtmax [MAXB*MAXK];      // float bits (>=0) via atomicMax
__device__ float              g_lb    [MAXB*MAXK];      // per-gt IoU lower bound
__device__ float              g_uw    [MAXB];
__device__ uint4              g_keys  [MAXB];           // (kf.x,kf.y,kb.x,kb.y)
__device__ int                g_cnt   [MAXB*2];         // fg,bg candidate counts
__device__ unsigned long long g_fg    [MAXB*NANCH];     // (prio<<32)|orig_n
__device__ unsigned long long g_bg    [MAXB*NANCH];

// 9 base anchors (exact integers), order: ratio {0.5,1,2} x scale {8,16,32}
__constant__ float c_base[36] = {
  -84.f, -40.f,  99.f,  55.f,
 -176.f, -88.f, 191.f, 103.f,
 -360.f,-184.f, 375.f, 199.f,
  -56.f, -56.f,  71.f,  71.f,
 -120.f,-120.f, 135.f, 135.f,
 -248.f,-248.f, 263.f, 263.f,
  -36.f, -80.f,  51.f,  95.f,
  -80.f,-168.f,  95.f, 183.f,
 -168.f,-344.f, 183.f, 359.f
};

// ---------------- threefry2x32 (20 rounds), matches jax threefry2x32_p -------
__device__ __forceinline__ void tf_round(unsigned &x0, unsigned &x1, int r){
  x0 += x1; x1 = (x1 << r) | (x1 >> (32 - r)); x1 ^= x0;
}
__device__ __forceinline__ uint2 threefry(unsigned k0, unsigned k1,
                                          unsigned x0, unsigned x1){
  unsigned k2 = k0 ^ k1 ^ 0x1BD11BDAu;
  x0 += k0; x1 += k1;
  tf_round(x0,x1,13); tf_round(x0,x1,15); tf_round(x0,x1,26); tf_round(x0,x1,6);
  x0 += k1; x1 += k2 + 1u;
  tf_round(x0,x1,17); tf_round(x0,x1,29); tf_round(x0,x1,16); tf_round(x0,x1,24);
  x0 += k2; x1 += k0 + 2u;
  tf_round(x0,x1,13); tf_round(x0,x1,15); tf_round(x0,x1,26); tf_round(x0,x1,6);
  x0 += k0; x1 += k1 + 3u;
  tf_round(x0,x1,17); tf_round(x0,x1,29); tf_round(x0,x1,16); tf_round(x0,x1,24);
  x0 += k1; x1 += k2 + 4u;
  tf_round(x0,x1,13); tf_round(x0,x1,15); tf_round(x0,x1,26); tf_round(x0,x1,6);
  x0 += k2; x1 += k0 + 5u;
  return make_uint2(x0, x1);
}
__device__ __forceinline__ unsigned uniform_m23(unsigned k0, unsigned k1, unsigned idx){
  uint2 r = threefry(k0, k1, 0u, idx);
  return (r.x ^ r.y) >> 9;   // 23-bit mantissa bits; monotone in the uniform value
}

// exact IoU with reference rounding (strict rn ops, no fma contraction)
__device__ __forceinline__ float iou_exact(float ax1,float ay1,float ax2,float ay2,
                                           float aarea,
                                           float g0,float g1,float g2,float g3,float ga){
  float ix = fmaxf(0.f, __fadd_rn(__fsub_rn(fminf(ax2,g2), fmaxf(ax1,g0)),1.f));
  float iy = fmaxf(0.f, __fadd_rn(__fsub_rn(fminf(ay2,g3), fmaxf(ay1,g1)),1.f));
  float inter = __fmul_rn(ix, iy);
  float uni   = __fsub_rn(__fadd_rn(aarea, ga), inter);
  return __fdiv_rn(inter, uni);
}

// ---------------- kernel 0: init + PRNG keys + per-gt LB ---------------------
__global__ void k_pre(const float* __restrict__ gt, const float* __restrict__ iminfo, int K){
  int b = blockIdx.x, t = threadIdx.x;
  if (t < MAXK) g_gtmax[b*MAXK+t] = 0;
  if (t < 2)    g_cnt[b*2+t] = 0;
  if (t == 0){
    // jax.random.key(42) -> (0,42); foldlike split: key_b = block(root, 0, b)
    uint2 root = threefry(0u, 42u, 0u, (unsigned)b);
    uint2 kf = threefry(root.x, root.y, 0u, 0u);
    uint2 kb = threefry(root.x, root.y, 0u, 1u);
    g_keys[b] = make_uint4(kf.x, kf.y, kb.x, kb.y);
  }
  if (t < K){
    float imh = iminfo[0], imw = iminfo[1];
    float g0 = gt[(b*K+t)*5+0], g1 = gt[(b*K+t)*5+1];
    float g2 = gt[(b*K+t)*5+2], g3 = gt[(b*K+t)*5+3];
    float ga = __fmul_rn(__fadd_rn(__fsub_rn(g2,g0),1.f),
                         __fadd_rn(__fsub_rn(g3,g1),1.f));
    float gcx = 0.5f*(g0+g2), gcy = 0.5f*(g1+g3);
    float lb = 0.f;
    for (int a = 0; a < A_LOC; a++){
      float bx1 = c_base[a*4+0], by1 = c_base[a*4+1];
      float bx2 = c_base[a*4+2], by2 = c_base[a*4+3];
      int xlo = (int)ceilf(-bx1/16.f);          if (xlo < 0)  xlo = 0;
      int xhi = (int)ceilf((imw-bx2)/16.f) - 1; if (xhi > 63) xhi = 63;
      int ylo = (int)ceilf(-by1/16.f);          if (ylo < 0)  ylo = 0;
      int yhi = (int)ceilf((imh-by2)/16.f) - 1; if (yhi > 63) yhi = 63;
      if (xlo > xhi || ylo > yhi) continue;
      int xc = (int)floorf((gcx - 7.5f)/16.f);
      int yc = (int)floorf((gcy - 7.5f)/16.f);
      for (int dy = 0; dy < 2; dy++){
        int y = yc + dy; y = y < ylo ? ylo : (y > yhi ? yhi : y);
        for (int dx = 0; dx < 2; dx++){
          int x = xc + dx; x = x < xlo ? xlo : (x > xhi ? xhi : x);
          float ax1 = bx1 + 16.f*(float)x, ay1 = by1 + 16.f*(float)y;
          float ax2 = bx2 + 16.f*(float)x, ay2 = by2 + 16.f*(float)y;
          float aw = __fadd_rn(__fsub_rn(ax2,ax1),1.f);
          float ah = __fadd_rn(__fsub_rn(ay2,ay1),1.f);
          float aarea = __fmul_rn(aw, ah);
          float o = iou_exact(ax1,ay1,ax2,ay2,aarea, g0,g1,g2,g3,ga);
          if (o > lb) lb = o;
        }
      }
    }
    g_lb[b*MAXK+t] = lb;
  }
}

// ---------------- kernel 1: IoU, max/arg, gt_max, candidate record -----------
__global__ void k_iou(const float* __restrict__ gt, const float* __restrict__ iminfo, int K){
  int b = blockIdx.y;
  __shared__ float sgx1[MAXK], sgy1[MAXK], sgx2[MAXK], sgy2[MAXK], sga[MAXK], slb[MAXK];
  __shared__ int   s_gm[MAXK];
  int t = threadIdx.x;
  if (t < MAXK) s_gm[t] = 0;
  if (t < K){
    float g0 = gt[(b*K+t)*5+0], g1 = gt[(b*K+t)*5+1];
    float g2 = gt[(b*K+t)*5+2], g3 = gt[(b*K+t)*5+3];
    sgx1[t]=g0; sgy1[t]=g1; sgx2[t]=g2; sgy2[t]=g3;
    sga[t] = __fmul_rn(__fadd_rn(__fsub_rn(g2,g0),1.f),
                       __fadd_rn(__fsub_rn(g3,g1),1.f));
    slb[t] = g_lb[b*MAXK+t];
  }
  __syncthreads();

  int idx2 = blockIdx.x*blockDim.x + t;     // shape-major
  int a = idx2 >> 12, loc = idx2 & (LOCS-1);
  int x = loc & (HW-1), y = loc >> 6;
  float ax1 = c_base[a*4+0] + 16.f*(float)x;
  float ay1 = c_base[a*4+1] + 16.f*(float)y;
  float ax2 = c_base[a*4+2] + 16.f*(float)x;
  float ay2 = c_base[a*4+3] + 16.f*(float)y;
  float imh = iminfo[0], imw = iminfo[1];
  bool inside = (ax1 >= 0.f) && (ay1 >= 0.f) && (ax2 < imw) && (ay2 < imh);
  int sidx = b*NANCH + idx2;

  if (inside){
    float aw = __fadd_rn(__fsub_rn(ax2,ax1),1.f);
    float ah = __fadd_rn(__fsub_rn(ay2,ay1),1.f);
    float aarea = __fmul_rn(aw, ah);
    float mo = 0.f; int ma = 0, ccnt = 0;
    for (int k = 0; k < K; k++){
      float ix = __fadd_rn(__fsub_rn(fminf(ax2,sgx2[k]), fmaxf(ax1,sgx1[k])),1.f);
      float iy = __fadd_rn(__fsub_rn(fminf(ay2,sgy2[k]), fmaxf(ay1,sgy1[k])),1.f);
      if (ix > 0.f && iy > 0.f){
        float inter = __fmul_rn(ix, iy);
        float uni   = __fsub_rn(__fadd_rn(aarea, sga[k]), inter);
        float ovr   = __fdiv_rn(inter, uni);
        if (ovr > mo){ mo = ovr; ma = k; }
        if (ovr >= slb[k]){                       // can only tie gt_max if >= LB
          unsigned bits = (unsigned)__float_as_int(ovr);
          atomicMax(&s_gm[k], (int)bits);
          if (ccnt < SLOTS)
            g_cand[(size_t)sidx*SLOTS + ccnt] = ((unsigned long long)bits << 32) | (unsigned)k;
          ccnt++;
        }
      }
    }
    g_maxovr[sidx] = mo;
    g_arg   [sidx] = (unsigned char)ma;
    g_ccnt  [sidx] = (unsigned char)(ccnt > 255 ? 255 : ccnt);
  } else {
    g_maxovr[sidx] = -1.f;
  }
  __syncthreads();
  if (t < K && s_gm[t]) atomicMax(&g_gtmax[b*MAXK+t], s_gm[t]);
}

// ---------------- kernel 2: labels from candidates + compaction --------------
__global__ void k_label(const float* __restrict__ gt, int K){
  int b = blockIdx.y;
  __shared__ float sgx1[MAXK], sgy1[MAXK], sgx2[MAXK], sgy2[MAXK], sga[MAXK], sgm[MAXK];
  int t = threadIdx.x;
  if (t < K){
    float g0 = gt[(b*K+t)*5+0], g1 = gt[(b*K+t)*5+1];
    float g2 = gt[(b*K+t)*5+2], g3 = gt[(b*K+t)*5+3];
    sgx1[t]=g0; sgy1[t]=g1; sgx2[t]=g2; sgy2[t]=g3;
    sga[t] = __fmul_rn(__fadd_rn(__fsub_rn(g2,g0),1.f),
                       __fadd_rn(__fsub_rn(g3,g1),1.f));
    sgm[t] = __int_as_float(g_gtmax[b*MAXK+t]);   // 0 => no inside anchor hits this gt
  }
  __syncthreads();

  int idx2 = blockIdx.x*blockDim.x + t;
  int a = idx2 >> 12, loc = idx2 & (LOCS-1);
  int sidx = b*NANCH + idx2;
  float mo = g_maxovr[sidx];
  signed char L;
  if (mo < 0.f){
    L = -2;
  } else {
    L = (mo < 0.3f) ? 0 : -1;
    bool best = false;
    int cnt = (int)g_ccnt[sidx];
    if (cnt <= SLOTS){
      for (int i = 0; i < cnt; i++){
        unsigned long long e = g_cand[(size_t)sidx*SLOTS + i];
        int k = (int)(unsigned)e;
        float ovr = __uint_as_float((unsigned)(e >> 32));
        if (ovr == sgm[k]) best = true;
      }
    } else {
      // rare fallback: exact recompute with per-thread prune
      int x = loc & (HW-1), y = loc >> 6;
      float ax1 = c_base[a*4+0] + 16.f*(float)x;
      float ay1 = c_base[a*4+1] + 16.f*(float)y;
      float ax2 = c_base[a*4+2] + 16.f*(float)x;
      float ay2 = c_base[a*4+3] + 16.f*(float)y;
      float aw = __fadd_rn(__fsub_rn(ax2,ax1),1.f);
      float ah = __fadd_rn(__fsub_rn(ay2,ay1),1.f);
      float aarea = __fmul_rn(aw, ah);
      for (int k = 0; k < K; k++){
        float gm = sgm[k];
        if (gm <= 0.f || gm > mo) continue;
        float ovr = iou_exact(ax1,ay1,ax2,ay2,aarea,
                              sgx1[k],sgy1[k],sgx2[k],sgy2[k],sga[k]);
        if (ovr == gm) best = true;
      }
    }
    if (best) L = 1;
    if (mo >= 0.7f) L = 1;
  }
  g_lbl[sidx] = L;

  // ---- fused candidate compaction (warp-aggregated global append) ----
  int n = loc*A_LOC + a;                        // ORIGINAL anchor index
  bool isfg = (L == 1), isbg = (L == 0);
  unsigned mfg = __ballot_sync(0xffffffffu, isfg);
  unsigned mbg = __ballot_sync(0xffffffffu, isbg);
  int lane = t & 31;
  if (isfg){
    uint4 kk = g_keys[b];
    unsigned prio = uniform_m23(kk.x, kk.y, (unsigned)n);
    int ldr = __ffs(mfg) - 1;
    int pos;
    if (lane == ldr) pos = atomicAdd(&g_cnt[b*2+0], __popc(mfg));
    pos = __shfl_sync(mfg, pos, ldr);
    pos += __popc(mfg & ((1u << lane) - 1u));
    g_fg[b*NANCH + pos] = ((unsigned long long)prio << 32) | (unsigned)n;
  }
  if (isbg){
    uint4 kk = g_keys[b];
    unsigned prio = uniform_m23(kk.z, kk.w, (unsigned)n);
    int ldr = __ffs(mbg) - 1;
    int pos;
    if (lane == ldr) pos = atomicAdd(&g_cnt[b*2+1], __popc(mbg));
    pos = __shfl_sync(mbg, pos, ldr);
    pos += __popc(mbg & ((1u << lane) - 1u));
    g_bg[b*NANCH + pos] = ((unsigned long long)prio << 32) | (unsigned)n;
  }
}

// ---------------- kernel 3: per-batch subsampling on compacted lists ---------
__device__ __forceinline__ int suffix_scan1024(int v, int* s_w){
  int tid = threadIdx.x, lane = tid & 31, wrp = tid >> 5;
  int s = v;
#pragma unroll
  for (int off = 1; off < 32; off <<= 1){
    int o = __shfl_down_sync(0xffffffffu, s, off);
    if (lane + off < 32) s += o;
  }
  if (lane == 0) s_w[wrp] = s;
  __syncthreads();
  if (wrp == 0){
    int tot = s_w[lane], s2 = tot;
#pragma unroll
    for (int off = 1; off < 32; off <<= 1){
      int o = __shfl_down_sync(0xffffffffu, s2, off);
      if (lane + off < 32) s2 += o;
    }
    s_w[lane] = s2 - tot;                       // sum of LATER warps
  }
  __syncthreads();
  return s + s_w[wrp];                          // suffix incl own value
}

__device__ __forceinline__ int sm_idx_of_n(int n){  // original n -> shape-major idx
  int a = n % A_LOC, loc = n / A_LOC;
  return a*LOCS + loc;
}

// Keep top-`limit` entries by (prio desc, index asc); disable the rest.
__device__ int do_select_list(const unsigned long long* __restrict__ list,
                              int b, int cnt, int limit,
                              int* hist, int* s_w, int* s_list, int* s_s){
  const int tid = threadIdx.x;
  if (cnt <= limit) return cnt;

  // --- level 1: 4096 bins on prio[22:11]
  for (int i = tid; i < 4096; i += 1024) hist[i] = 0;
  __syncthreads();
  for (int i = tid; i < cnt; i += 1024)
    atomicAdd(&hist[(unsigned)(list[i] >> 32) >> 11], 1);
  __syncthreads();
  int v = hist[4*tid] + hist[4*tid+1] + hist[4*tid+2] + hist[4*tid+3];
  int S = suffix_scan1024(v, s_w);
  if (S >= limit && S - v < limit){ s_s[0] = tid; s_s[1] = S - v; }
  __syncthreads();
  if (tid == 0){
    int g = s_s[0], acc = s_s[1];
    for (int q = 4*g+3; q >= 4*g; q--){
      acc += hist[q];
      if (acc >= limit){ s_s[2] = q; s_s[3] = limit - (acc - hist[q]); break; }
    }
  }
  __syncthreads();
  int bin = s_s[2], rem = s_s[3];

  // --- level 2: 2048 bins on prio[10:0] within boundary bin
  for (int i = tid; i < 2048; i += 1024) hist[i] = 0;
  __syncthreads();
  for (int i = tid; i < cnt; i += 1024){
    unsigned p = (unsigned)(list[i] >> 32);
    if ((int)(p >> 11) == bin) atomicAdd(&hist[p & 2047], 1);
  }
  __syncthreads();
  v = hist[2*tid] + hist[2*tid+1];
  S = suffix_scan1024(v, s_w);
  if (S >= rem && S - v < rem){ s_s[0] = tid; s_s[1] = S - v; }
  __syncthreads();
  if (tid == 0){
    int g = s_s[0], acc = s_s[1];
    for (int u = 2*g+1; u >= 2*g; u--){
      acc += hist[u];
      if (acc >= rem){ s_s[4] = (bin << 11) | u; s_s[5] = rem - (acc - hist[u]); break; }
    }
    s_s[6] = 0;
  }
  __syncthreads();
  unsigned tval = (unsigned)s_s[4]; int r = s_s[5];

  // --- mark below-threshold disabled, collect exact ties
  for (int i = tid; i < cnt; i += 1024){
    unsigned long long e = list[i];
    unsigned p = (unsigned)(e >> 32);
    int n = (int)(unsigned)e;
    if (p < tval) g_lbl[b*NANCH + sm_idx_of_n(n)] = -1;
    else if (p == tval){
      int pos = atomicAdd(&s_s[6], 1);
      if (pos < 512) s_list[pos] = n;
    }
  }
  __syncthreads();
  if (tid == 0){
    int ec = s_s[6]; if (ec > 512) ec = 512;
    for (int i = 1; i < ec; i++){               // insertion sort asc (ec tiny)
      int vv = s_list[i]; int j = i - 1;
      while (j >= 0 && s_list[j] > vv){ s_list[j+1] = s_list[j]; j--; }
      s_list[j+1] = vv;
    }
    for (int j = r; j < ec; j++) g_lbl[b*NANCH + sm_idx_of_n(s_list[j])] = -1;
  }
  __syncthreads();
  return limit;
}

__global__ void k_sub(){
  int b = blockIdx.x;
  __shared__ int hist[4096];
  __shared__ int s_w[32];
  __shared__ int s_list[512];
  __shared__ int s_s[8];
  int cf = g_cnt[b*2+0];
  int cb = g_cnt[b*2+1];
  int kept_fg = do_select_list(&g_fg[b*NANCH], b, cf, 128, hist, s_w, s_list, s_s);
  int kept_bg = do_select_list(&g_bg[b*NANCH], b, cb, 256 - kept_fg, hist, s_w, s_list, s_s);
  if (threadIdx.x == 0)
    g_uw[b] = __fdiv_rn(1.f, (float)(kept_fg + kept_bg));
}

// ---------------- kernel 4: targets + transposed output writer ---------------
__global__ void k_out(const float* __restrict__ gt, float* __restrict__ out, int B, int K){
  int b = blockIdx.z, a = blockIdx.y;
  int loc = blockIdx.x*blockDim.x + threadIdx.x;
  __shared__ float s_g[MAXK][4];
  if (threadIdx.x < K){
    int t = threadIdx.x;
    s_g[t][0] = gt[(b*K+t)*5+0]; s_g[t][1] = gt[(b*K+t)*5+1];
    s_g[t][2] = gt[(b*K+t)*5+2]; s_g[t][3] = gt[(b*K+t)*5+3];
  }
  __syncthreads();

  int sidx = b*NANCH + a*LOCS + loc;            // shape-major
  signed char L = g_lbl[sidx];
  float lab = (L == -2) ? 0.f : (float)L;

  size_t labOff = (size_t)b*NANCH + (size_t)a*LOCS + loc;
  out[labOff] = lab;

  float t0=0.f, t1=0.f, t2=0.f, t3=0.f, iw=0.f, ow=0.f;
  if (L != -2){
    int x = loc & (HW-1), y = loc >> 6;
    float ax1 = c_base[a*4+0] + 16.f*(float)x;
    float ay1 = c_base[a*4+1] + 16.f*(float)y;
    float ax2 = c_base[a*4+2] + 16.f*(float)x;
    float ay2 = c_base[a*4+3] + 16.f*(float)y;
    float aw = ax2-ax1+1.f, ah = ay2-ay1+1.f;
    float acx = ax1 + 0.5f*(aw-1.f), acy = ay1 + 0.5f*(ah-1.f);
    int k = g_arg[sidx];
    float g0 = s_g[k][0], g1 = s_g[k][1], g2 = s_g[k][2], g3 = s_g[k][3];
    float gw = g2-g0+1.f, gh = g3-g1+1.f;
    float gcx = g0 + 0.5f*(gw-1.f), gcy = g1 + 0.5f*(gh-1.f);
    t0 = (gcx-acx)/aw; t1 = (gcy-acy)/ah;
    t2 = logf(gw/aw);  t3 = logf(gh/ah);
    iw = (L == 1) ? 1.f : 0.f;
    ow = (L == 0 || L == 1) ? g_uw[b] : 0.f;
  }
  size_t base_t  = (size_t)B*NANCH;
  size_t planes  = (size_t)B*36*LOCS;
  size_t p       = ((size_t)b*36 + (size_t)a*4)*LOCS + loc;
  float tv[4] = {t0,t1,t2,t3};
#pragma unroll
  for (int j = 0; j < 4; j++){
    out[base_t              + p + (size_t)j*LOCS] = tv[j];
    out[base_t +   planes   + p + (size_t)j*LOCS] = iw;
    out[base_t + 2*planes   + p + (size_t)j*LOCS] = ow;
  }
}

// ---------------- launch -----------------------------------------------------
extern "C" void kernel_launch(void* const* d_in, const int* in_sizes, int n_in,
                              void* d_out, int out_size){
  const float* gt     = (const float*)d_in[1];
  const float* iminfo = (const float*)d_in[2];
  float* out = (float*)d_out;

  int B = in_sizes[0] / (2*A_LOC*LOCS);     // rpn_cls_score: B x 18 x 64 x 64
  int K = in_sizes[1] / (5*B);              // gt_boxes:      B x K x 5
  if (B > MAXB) B = MAXB;
  if (K > MAXK) K = MAXK;

  k_pre<<<B, MAXK>>>(gt, iminfo, K);
  dim3 g1(NANCH/256, B);
  k_iou  <<<g1, 256>>>(gt, iminfo, K);
  k_label<<<g1, 256>>>(gt, K);
  k_sub  <<<B, 1024>>>();
  k_out  <<<dim3(LOCS/256, A_LOC, B), 256>>>(gt, out, B, K);
}